// round 14
// baseline (speedup 1.0000x reference)
#include <cuda_runtime.h>
#include <math.h>

#define HH 1024
#define WW 1024
#define NPIX (HH * WW)
#define NWORDS 32                 // packed words per row
#define RPB 8                     // output rows per block in kernel A
#define LROWS (RPB + 4)           // seg rows loaded: r0-2 .. r0+9
#define EROWS (RPB + 2)           // edge rows computed: r0-1 .. r0+8

#define B_BLOCKS 64               // x-blocks per image in kernel B
#define B_THREADS 1024
#define B_ITERS (NPIX / 4 / (B_BLOCKS * B_THREADS))   // 4
#define NBLK_TOTAL (B_BLOCKS * 2)                     // 128
#define FIXSCALE 1048576.0        // 2^20 fixed point

// Scratch (no allocations allowed anywhere)
__device__ unsigned int       g_edgebits[2][HH * NWORDS];  // 256 KB
__device__ unsigned char      g_D[2][NPIX];                // 2 MB: D2 code 0..4, 255=unresolved
__device__ unsigned long long g_acc;   // [63:48] block count, [47:0] fixed-point sum

__device__ __forceinline__ unsigned horiz3(unsigned wv, unsigned wl, unsigned wr) {
    return wv & ((wv << 1) | (wl >> 31)) & ((wv >> 1) | (wr << 31));
}

// exact per-row nearest-edge distance from the packed edge bitmap (global),
// replicating the reference's 1e6 fp32 defaults bit-for-bit. Rare path only.
__device__ float row_g(const unsigned* __restrict__ row, int c)
{
    const int t = c >> 5, k = c & 31;
    const unsigned wc = row[t];
    const unsigned wl = (t > 0) ? row[t - 1] : 0u;
    const unsigned wr2 = (t < NWORDS - 1) ? row[t + 1] : 0u;
    const unsigned long long L = ((unsigned long long)wc << 32) | wl;   // pixel at bit 32+k
    const unsigned long long R = ((unsigned long long)wr2 << 32) | wc;  // pixel at bit k
    const unsigned long long lm = L & (~0ULL >> (31 - k));
    const unsigned long long rm = R & (~0ULL << k);
    float dl, dr;
    if (lm) {
        dl = (float)(__clzll((long long)lm) - (31 - k));
    } else {
        int tt = t - 2;
        while (tt >= 0 && row[tt] == 0u) tt--;
        if (tt >= 0) dl = (float)(c - (tt * 32 + (31 - __clz(row[tt]))));
        else         dl = (float)c + 1e6f;          // reference default, exact fp32
    }
    if (rm) {
        dr = (float)(__ffsll((long long)rm) - 1 - k);
    } else {
        int tt = t + 2;
        while (tt < NWORDS && row[tt] == 0u) tt++;
        if (tt < NWORDS) dr = (float)((tt * 32 + (__ffs(row[tt]) - 1)) - c);
        else             dr = 1e6f - (float)c;      // reference default, exact fp32
    }
    return fminf(fminf(dl, dr), 1e6f);
}

// exact column lower-envelope for one pixel, recomputed from edge bits.
// Same candidates/prune as the reference (d^2 >= best cannot improve, g2>=0).
__device__ float edt2_exact(const unsigned* __restrict__ eb, int r, int c)
{
    float g = row_g(eb + r * NWORDS, c);
    float best = g * g;
    for (int d = 1;; d++) {
        const float dd = (float)(d * d);
        if (dd >= best) break;
        bool any = false;
        if (r - d >= 0) { const float gu = row_g(eb + (r - d) * NWORDS, c); best = fminf(best, gu * gu + dd); any = true; }
        if (r + d < HH) { const float gd = row_g(eb + (r + d) * NWORDS, c); best = fminf(best, gd * gd + dd); any = true; }
        if (!any) break;
    }
    return best;
}

// ---------------------------------------------------------------------------
// Kernel A: bit-packed edges + per-row 1D distance + VERTICAL DEPTH-1 MIN,
// emitting a u8 code per pixel: D2 = min(g2[r], min(g2[r-1],g2[r+1])+1).
// D2 <= 4 proves global optimality (all d>=2 candidates >= 4) and D2 is then
// an exact small integer -> code 0..4; otherwise 255 (resolved exactly in B).
// The depth-1 min is pure register work (sliding 3-value window over the
// per-thread row loop). Loads RPB+4 seg rows, computes RPB+2 edge rows.
// ---------------------------------------------------------------------------
__global__ void __launch_bounds__(WW, 2) edges_rowdist_kernel(
    const float* __restrict__ preds, const float* __restrict__ targets)
{
    const int r0 = blockIdx.x * RPB;
    const int m  = blockIdx.y;
    const int j  = threadIdx.x;
    const float* __restrict__ seg = (m == 0) ? preds : targets;

    // reset the packed accumulator for this replay (stream-ordered before B)
    if (blockIdx.x == 0 && m == 0 && j == 0) g_acc = 0ULL;

    __shared__ unsigned shB[LROWS][NWORDS];
    __shared__ unsigned shE[EROWS][NWORDS];

    const int t = j >> 5, k = j & 31;

    // load LROWS rows (batched for MLP), ballot-pack to bits
    float v[LROWS];
    #pragma unroll
    for (int rr = 0; rr < LROWS; rr++) {
        const int row = r0 + rr - 2;
        v[rr] = (row >= 0 && row < HH) ? seg[row * WW + j] : 0.0f;
    }
    #pragma unroll
    for (int rr = 0; rr < LROWS; rr++) {
        const unsigned b = __ballot_sync(0xffffffffu, v[rr] == 1.0f);
        if (k == 0) shB[rr][t] = b;
    }
    __syncthreads();

    // EROWS*NWORDS = 320 threads compute one edge word each
    if (j < EROWS * NWORDS) {
        const int w  = j & (NWORDS - 1);
        const int rr = j >> 5;            // 0..9 -> edge row r0-1+rr
        const unsigned hp = horiz3(shB[rr][w],
                                   w > 0 ? shB[rr][w - 1] : 0u,
                                   w < NWORDS - 1 ? shB[rr][w + 1] : 0u);
        const unsigned hc = horiz3(shB[rr + 1][w],
                                   w > 0 ? shB[rr + 1][w - 1] : 0u,
                                   w < NWORDS - 1 ? shB[rr + 1][w + 1] : 0u);
        const unsigned hn = horiz3(shB[rr + 2][w],
                                   w > 0 ? shB[rr + 2][w - 1] : 0u,
                                   w < NWORDS - 1 ? shB[rr + 2][w + 1] : 0u);
        const unsigned e = shB[rr + 1][w] & ~(hp & hc & hn);
        shE[rr][w] = e;
        // store edge words only for center rows r0..r0+RPB-1
        if (rr >= 1 && rr <= RPB)
            g_edgebits[m][(r0 + rr - 1) * NWORDS + w] = e;
    }
    __syncthreads();

    // per-pixel nearest edge per row (R6 search) + sliding vertical depth-1 min
    float prev2 = 0.0f, prev1 = 0.0f;
    #pragma unroll
    for (int rr = 0; rr < EROWS; rr++) {
        const unsigned ew = shE[rr][t];
        float g;
        if ((ew >> k) & 1u) {
            g = 0.0f;
        } else {
            float dl;
            const unsigned lw = (k > 0) ? (ew & ((1u << k) - 1u)) : 0u;
            if (lw) {
                dl = (float)(k - (31 - __clz(lw)));
            } else {
                int tt = t - 1;
                while (tt >= 0 && shE[rr][tt] == 0u) tt--;
                if (tt >= 0) dl = (float)(j - (tt * 32 + (31 - __clz(shE[rr][tt]))));
                else         dl = (float)j + 1e6f;
            }
            float dr;
            const unsigned rw = (k < 31) ? (ew & (0xFFFFFFFEu << k)) : 0u;
            if (rw) {
                dr = (float)(__ffs(rw) - 1 - k);
            } else {
                int tt = t + 1;
                while (tt < NWORDS && shE[rr][tt] == 0u) tt++;
                if (tt < NWORDS) dr = (float)((tt * 32 + (__ffs(shE[rr][tt]) - 1)) - j);
                else             dr = 1e6f - (float)j;
            }
            g = fminf(fminf(dl, dr), 1e6f);
        }
        const int gr = r0 - 1 + rr;                  // global row of this g
        const float cur = (gr >= 0 && gr < HH) ? g * g : 3e37f;

        if (rr >= 2) {
            // center row = r0 + rr - 2, value prev1; neighbors prev2 / cur
            const float dmin = fminf(prev1, fminf(prev2, cur) + 1.0f);
            g_D[m][(r0 + rr - 2) * WW + j] =
                (dmin <= 4.0f) ? (unsigned char)(int)dmin : (unsigned char)255;
        }
        prev2 = prev1; prev1 = cur;
    }
}

// ---------------------------------------------------------------------------
// Kernel B: byte-stream histogram. Per u32 word (4 pixels): expand the 4 mask
// bits to byte lanes, then VCMPEQ4/POPC count codes 1..4 (code 0 adds 0).
// sum = n1*1 + n2*sqrt2 + n3*sqrt3 + n4*2 (+ exact recompute for rare 255s),
// assembled once per block in double from exact integer counts ->
// bit-deterministic. Final reduction fused via one packed u64 atomic.
// ---------------------------------------------------------------------------
__global__ void __launch_bounds__(B_THREADS) countpass_kernel(float* __restrict__ out)
{
    const int m   = blockIdx.y;
    const int tid = threadIdx.x;
    const unsigned* __restrict__ Dw = (const unsigned*)g_D[m];
    const unsigned* __restrict__ Mw = g_edgebits[1 - m];
    const unsigned* __restrict__ Eb = g_edgebits[m];

    unsigned c1 = 0, c2 = 0, c3 = 0, c4 = 0;
    float racc = 0.0f;

    #pragma unroll
    for (int it = 0; it < B_ITERS; it++) {
        const int widx = it * (B_BLOCKS * B_THREADS) + blockIdx.x * B_THREADS + tid;
        const unsigned w     = Dw[widx];
        const unsigned mword = Mw[widx >> 3];
        const unsigned nib   = (mword >> ((widx & 7) * 4)) & 0xFu;
        const unsigned spread = (nib & 1u) | ((nib & 2u) << 7)
                              | ((nib & 4u) << 14) | ((nib & 8u) << 21);
        const unsigned mb = spread * 0xFFu;            // 0xFF per masked byte

        // rare: masked byte == 255 -> exact recompute from edge bitmaps
        unsigned un = w & mb & 0x80808080u;
        while (un) {
            const int bit = __ffs(un) - 1;
            un &= un - 1;
            const int p = widx * 4 + (bit >> 3);
            racc += sqrtf(edt2_exact(Eb, p >> 10, p & (WW - 1)));
        }

        c1 += __popc(__vcmpeq4(w, 0x01010101u) & mb);  // raw counts are 8x
        c2 += __popc(__vcmpeq4(w, 0x02020202u) & mb);
        c3 += __popc(__vcmpeq4(w, 0x03030303u) & mb);
        c4 += __popc(__vcmpeq4(w, 0x04040404u) & mb);
    }

    // pack counts (block max 16384 per field < 2^16) and reduce
    unsigned long long pc = (unsigned long long)(c1 >> 3)
                          | ((unsigned long long)(c2 >> 3) << 16)
                          | ((unsigned long long)(c3 >> 3) << 32)
                          | ((unsigned long long)(c4 >> 3) << 48);
    #pragma unroll
    for (int o = 16; o > 0; o >>= 1) {
        pc   += __shfl_down_sync(0xffffffffu, pc, o);
        racc += __shfl_down_sync(0xffffffffu, racc, o);
    }

    __shared__ unsigned long long wp[32];
    __shared__ float              wr[32];
    if ((tid & 31) == 0) { wp[tid >> 5] = pc; wr[tid >> 5] = racc; }
    __syncthreads();

    if (tid == 0) {
        unsigned long long tot = 0; float fr = 0.0f;
        #pragma unroll
        for (int i = 0; i < 32; i++) { tot += wp[i]; fr += wr[i]; }
        const double n1 = (double)(tot & 0xFFFFULL);
        const double n2 = (double)((tot >> 16) & 0xFFFFULL);
        const double n3 = (double)((tot >> 32) & 0xFFFFULL);
        const double n4 = (double)((tot >> 48) & 0xFFFFULL);
        const double bs = n1
                        + n2 * 1.4142135623730951
                        + n3 * 1.7320508075688772
                        + n4 * 2.0
                        + (double)fr;

        const unsigned long long vfix   = (unsigned long long)(bs * FIXSCALE + 0.5);
        const unsigned long long packed = (1ULL << 48) | vfix;
        const unsigned long long old    = atomicAdd(&g_acc, packed);

        if ((old >> 48) == (unsigned long long)(NBLK_TOTAL - 1)) {
            const unsigned long long total = (old & 0xFFFFFFFFFFFFULL) + vfix;
            const float loss =
                (float)((double)total * (1.0 / FIXSCALE)) / (2.0f * (float)NPIX);
            out[0] = 1.0f / (1.0f + expf(-loss));
        }
    }
}

// ---------------------------------------------------------------------------
extern "C" void kernel_launch(void* const* d_in, const int* in_sizes, int n_in,
                              void* d_out, int out_size)
{
    const float* preds   = (const float*)d_in[0];
    const float* targets = (const float*)d_in[1];
    float* out = (float*)d_out;
    (void)in_sizes; (void)n_in; (void)out_size;

    dim3 gridA(HH / RPB, 2);
    edges_rowdist_kernel<<<gridA, WW>>>(preds, targets);

    dim3 gridB(B_BLOCKS, 2);
    countpass_kernel<<<gridB, B_THREADS>>>(out);
}